// round 1
// baseline (speedup 1.0000x reference)
#include <cuda_runtime.h>
#include <cuda_bf16.h>
#include <math.h>

#define N_NODES 50000
#define N_EDGES 800000
#define NFEAT 256
#define NHID 64
#define NCLASS 2

// ---------------- scratch (static device globals; no allocation) ----------------
__device__ int   g_deg_src[N_NODES];
__device__ int   g_deg_dst[N_NODES];
__device__ float g_norm_src[N_NODES];
__device__ float g_norm_dst[N_NODES];
__device__ int   g_offsets[N_NODES + 1];
__device__ int   g_cursor[N_NODES];
__device__ int   g_csr[N_EDGES];           // src node id, bucketed by dst
__device__ float g_h [N_NODES * NHID];     // (x*norm_src)@W1
__device__ float g_h1[N_NODES * NHID];     // relu(agg*norm_dst+b1)*norm_src
__device__ float g_h2[N_NODES * NCLASS];   // h1@W2
__device__ int   g_is64;

// ---------------- index dtype handling ----------------
__device__ __forceinline__ int load_idx(const void* p, int i) {
    if (g_is64) return (int)((const long long*)p)[i];
    return ((const int*)p)[i];
}

__global__ void detect_kernel(const void* src) {
    if (threadIdx.x == 0 && blockIdx.x == 0) {
        const unsigned long long* p = (const unsigned long long*)src;
        int is64 = 1;
        for (int i = 0; i < 512; i++) {
            if (p[i] >= (unsigned long long)N_NODES) { is64 = 0; break; }
        }
        g_is64 = is64;
    }
}

// ---------------- degrees / norms ----------------
__global__ void zero_deg_kernel() {
    int i = blockIdx.x * blockDim.x + threadIdx.x;
    if (i < N_NODES) { g_deg_src[i] = 0; g_deg_dst[i] = 0; }
}

__global__ void count_deg_kernel(const void* src, const void* dst) {
    int e = blockIdx.x * blockDim.x + threadIdx.x;
    if (e < N_EDGES) {
        atomicAdd(&g_deg_src[load_idx(src, e)], 1);
        atomicAdd(&g_deg_dst[load_idx(dst, e)], 1);
    }
}

__global__ void norm_kernel() {
    int i = blockIdx.x * blockDim.x + threadIdx.x;
    if (i < N_NODES) {
        g_norm_src[i] = rsqrtf(fmaxf((float)g_deg_src[i], 1.0f));
        g_norm_dst[i] = rsqrtf(fmaxf((float)g_deg_dst[i], 1.0f));
    }
}

// ---------------- single-block exclusive scan of deg_dst -> offsets, cursor ----------------
__global__ void scan_kernel() {
    const int T = 1024;
    int tid = threadIdx.x;
    int per = (N_NODES + T - 1) / T;            // 49
    int start = tid * per;
    int end = min(start + per, N_NODES);
    int sum = 0;
    for (int i = start; i < end; i++) sum += g_deg_dst[i];

    __shared__ int warp_sums[32];
    int lane = tid & 31, wid = tid >> 5;
    int v = sum;
    #pragma unroll
    for (int off = 1; off < 32; off <<= 1) {
        int t = __shfl_up_sync(0xFFFFFFFFu, v, off);
        if (lane >= off) v += t;
    }
    if (lane == 31) warp_sums[wid] = v;
    __syncthreads();
    if (wid == 0) {
        int w = warp_sums[lane];
        #pragma unroll
        for (int off = 1; off < 32; off <<= 1) {
            int t = __shfl_up_sync(0xFFFFFFFFu, w, off);
            if (lane >= off) w += t;
        }
        warp_sums[lane] = w;
    }
    __syncthreads();
    int excl = (v - sum) + (wid > 0 ? warp_sums[wid - 1] : 0);
    int run = excl;
    for (int i = start; i < end; i++) {
        g_offsets[i] = run;
        g_cursor[i]  = run;
        run += g_deg_dst[i];
    }
    if (end == N_NODES) g_offsets[N_NODES] = run;
}

__global__ void csr_fill_kernel(const void* src, const void* dst) {
    int e = blockIdx.x * blockDim.x + threadIdx.x;
    if (e < N_EDGES) {
        int s = load_idx(src, e);
        int d = load_idx(dst, e);
        int pos = atomicAdd(&g_cursor[d], 1);
        g_csr[pos] = s;
    }
}

// ---------------- GEMM1: g_h = (x * norm_src) @ W1   [50000x256]x[256x64] ----------------
// Tile: 64 rows x 64 cols (all of N), K chunks of 32. 256 threads, 4x4 microtile.
#define TM 64
#define TK 32
__global__ void gemm1_kernel(const float* __restrict__ x, const float* __restrict__ W1) {
    __shared__ float As[TK][TM + 1];    // As[k][m], padded to kill store conflicts
    __shared__ float Bs[TK][NHID];      // Bs[k][n]

    int block_row = blockIdx.x * TM;
    int tid = threadIdx.x;
    int tx = tid & 15;          // 0..15 -> 4 cols each
    int ty = tid >> 4;          // 0..15 -> 4 rows each

    float acc[4][4] = {};

    for (int k0 = 0; k0 < NFEAT; k0 += TK) {
        // Load A tile: 64 rows x 32 k = 512 float4
        #pragma unroll
        for (int i = 0; i < 2; i++) {
            int idx = tid + i * 256;        // 0..511
            int r = idx >> 3;               // row in tile
            int c4 = idx & 7;               // float4 slot in k-chunk
            int grow = block_row + r;
            float4 vv = make_float4(0.f, 0.f, 0.f, 0.f);
            if (grow < N_NODES) {
                vv = *(const float4*)(x + (size_t)grow * NFEAT + k0 + c4 * 4);
                float nrm = g_norm_src[grow];
                vv.x *= nrm; vv.y *= nrm; vv.z *= nrm; vv.w *= nrm;
            }
            As[c4 * 4 + 0][r] = vv.x;
            As[c4 * 4 + 1][r] = vv.y;
            As[c4 * 4 + 2][r] = vv.z;
            As[c4 * 4 + 3][r] = vv.w;
        }
        // Load B tile: 32 k x 64 cols = 512 float4
        #pragma unroll
        for (int i = 0; i < 2; i++) {
            int idx = tid + i * 256;
            int kk = idx >> 4;              // 0..31
            int c4 = idx & 15;              // 0..15
            float4 vv = *(const float4*)(W1 + (size_t)(k0 + kk) * NHID + c4 * 4);
            *(float4*)&Bs[kk][c4 * 4] = vv;
        }
        __syncthreads();

        #pragma unroll
        for (int kk = 0; kk < TK; kk++) {
            float a[4];
            #pragma unroll
            for (int i = 0; i < 4; i++) a[i] = As[kk][ty * 4 + i];
            float4 bv = *(float4*)&Bs[kk][tx * 4];
            float b[4] = {bv.x, bv.y, bv.z, bv.w};
            #pragma unroll
            for (int i = 0; i < 4; i++)
                #pragma unroll
                for (int j = 0; j < 4; j++)
                    acc[i][j] = fmaf(a[i], b[j], acc[i][j]);
        }
        __syncthreads();
    }

    #pragma unroll
    for (int i = 0; i < 4; i++) {
        int grow = block_row + ty * 4 + i;
        if (grow < N_NODES) {
            float4 vv = make_float4(acc[i][0], acc[i][1], acc[i][2], acc[i][3]);
            *(float4*)(g_h + (size_t)grow * NHID + tx * 4) = vv;
        }
    }
}

// ---------------- AGG1: per-dst segmented sum of g_h[src], fused relu/bias/norms ----------------
// One warp per node; lane handles 2 features (float2).
__global__ void agg1_kernel(const float* __restrict__ b1) {
    int gw = (blockIdx.x * blockDim.x + threadIdx.x) >> 5;
    int lane = threadIdx.x & 31;
    if (gw >= N_NODES) return;
    int n = gw;
    int beg = g_offsets[n], end = g_offsets[n + 1];
    float2 acc = make_float2(0.f, 0.f);
    int i = beg;
    // 2-way unroll for MLP
    for (; i + 1 < end; i += 2) {
        int s0 = g_csr[i], s1 = g_csr[i + 1];
        float2 v0 = *(const float2*)(g_h + (size_t)s0 * NHID + lane * 2);
        float2 v1 = *(const float2*)(g_h + (size_t)s1 * NHID + lane * 2);
        acc.x += v0.x + v1.x;
        acc.y += v0.y + v1.y;
    }
    if (i < end) {
        int s0 = g_csr[i];
        float2 v0 = *(const float2*)(g_h + (size_t)s0 * NHID + lane * 2);
        acc.x += v0.x;
        acc.y += v0.y;
    }
    float nd = g_norm_dst[n], ns = g_norm_src[n];
    float o0 = fmaxf(fmaf(acc.x, nd, b1[lane * 2 + 0]), 0.f) * ns;
    float o1 = fmaxf(fmaf(acc.y, nd, b1[lane * 2 + 1]), 0.f) * ns;
    *(float2*)(g_h1 + (size_t)n * NHID + lane * 2) = make_float2(o0, o1);
}

// ---------------- Layer2 GEMM: g_h2 = g_h1 @ W2  (K=64, C=2), one warp per node ----------------
__global__ void layer2_kernel(const float* __restrict__ W2) {
    int gw = (blockIdx.x * blockDim.x + threadIdx.x) >> 5;
    int lane = threadIdx.x & 31;
    if (gw >= N_NODES) return;
    int n = gw;
    float a0 = g_h1[(size_t)n * NHID + lane];
    float a1 = g_h1[(size_t)n * NHID + 32 + lane];
    float w00 = __ldg(&W2[lane * 2 + 0]);
    float w01 = __ldg(&W2[lane * 2 + 1]);
    float w10 = __ldg(&W2[(32 + lane) * 2 + 0]);
    float w11 = __ldg(&W2[(32 + lane) * 2 + 1]);
    float c0 = a0 * w00 + a1 * w10;
    float c1 = a0 * w01 + a1 * w11;
    #pragma unroll
    for (int off = 16; off > 0; off >>= 1) {
        c0 += __shfl_down_sync(0xFFFFFFFFu, c0, off);
        c1 += __shfl_down_sync(0xFFFFFFFFu, c1, off);
    }
    if (lane == 0) *(float2*)(g_h2 + (size_t)n * NCLASS) = make_float2(c0, c1);
}

// ---------------- AGG2 + log_softmax ----------------
__global__ void agg2_softmax_kernel(const float* __restrict__ b2, float* __restrict__ out) {
    int n = blockIdx.x * blockDim.x + threadIdx.x;
    if (n >= N_NODES) return;
    int beg = g_offsets[n], end = g_offsets[n + 1];
    float s0 = 0.f, s1 = 0.f;
    for (int i = beg; i < end; i++) {
        int s = g_csr[i];
        float2 v = *(const float2*)(g_h2 + (size_t)s * NCLASS);
        s0 += v.x; s1 += v.y;
    }
    float nd = g_norm_dst[n];
    float l0 = fmaf(s0, nd, b2[0]);
    float l1 = fmaf(s1, nd, b2[1]);
    float m = fmaxf(l0, l1);
    float lse = m + logf(expf(l0 - m) + expf(l1 - m));
    out[n * 2 + 0] = l0 - lse;
    out[n * 2 + 1] = l1 - lse;
}

// ---------------- launch ----------------
extern "C" void kernel_launch(void* const* d_in, const int* in_sizes, int n_in,
                              void* d_out, int out_size) {
    const float* x  = (const float*)d_in[0];
    const void*  src = d_in[1];
    const void*  dst = d_in[2];
    const float* W1 = (const float*)d_in[3];
    const float* b1 = (const float*)d_in[4];
    const float* W2 = (const float*)d_in[5];
    const float* b2 = (const float*)d_in[6];
    float* out = (float*)d_out;

    detect_kernel<<<1, 32>>>(src);
    zero_deg_kernel<<<(N_NODES + 255) / 256, 256>>>();
    count_deg_kernel<<<(N_EDGES + 255) / 256, 256>>>(src, dst);
    norm_kernel<<<(N_NODES + 255) / 256, 256>>>();
    scan_kernel<<<1, 1024>>>();
    csr_fill_kernel<<<(N_EDGES + 255) / 256, 256>>>(src, dst);

    gemm1_kernel<<<(N_NODES + TM - 1) / TM, 256>>>(x, W1);
    agg1_kernel<<<(N_NODES * 32 + 255) / 256, 256>>>(b1);
    layer2_kernel<<<(N_NODES * 32 + 255) / 256, 256>>>(W2);
    agg2_softmax_kernel<<<(N_NODES + 255) / 256, 256>>>(b2, out);
}

// round 2
// speedup vs baseline: 1.1138x; 1.1138x over previous
#include <cuda_runtime.h>
#include <cuda_bf16.h>
#include <math.h>

#define N_NODES 50000
#define N_EDGES 800000
#define NFEAT 256
#define NHID 64
#define NCLASS 2

// ---------------- scratch (static device globals; no allocation) ----------------
__device__ int   g_deg_src[N_NODES];
__device__ int   g_deg_dst[N_NODES];
__device__ float g_norm_src[N_NODES];
__device__ float g_norm_dst[N_NODES];
__device__ int   g_offsets[N_NODES + 1];
__device__ int   g_cursor[N_NODES];
__device__ int   g_csr[N_EDGES];           // src node id, bucketed by dst
__device__ float g_h [N_NODES * NHID];     // (x@W1)*norm_src
__device__ float g_h2[N_NODES * NCLASS];   // per-node layer2 logits (pre-agg)
__device__ int   g_is64;

// ---------------- index dtype handling ----------------
__device__ __forceinline__ int load_idx(const void* p, int i) {
    if (g_is64) return (int)((const long long*)p)[i];
    return ((const int*)p)[i];
}

// ---------------- init: zero degrees + detect index width ----------------
__global__ void init_kernel(const void* src) {
    int i = blockIdx.x * blockDim.x + threadIdx.x;
    if (i < N_NODES) { g_deg_src[i] = 0; g_deg_dst[i] = 0; }
    if (blockIdx.x == 0 && threadIdx.x < 32) {
        // interpret first 512 u64 words; if buffer is int32, high halves make
        // values >= N_NODES with overwhelming probability.
        const unsigned long long* p = (const unsigned long long*)src;
        int lane = threadIdx.x;
        int bad = 0;
        #pragma unroll
        for (int j = 0; j < 16; j++) {
            if (p[lane * 16 + j] >= (unsigned long long)N_NODES) bad = 1;
        }
        unsigned m = __ballot_sync(0xFFFFFFFFu, bad);
        if (lane == 0) g_is64 = (m == 0u) ? 1 : 0;
    }
}

__global__ void count_deg_kernel(const void* src, const void* dst) {
    int e = blockIdx.x * blockDim.x + threadIdx.x;
    if (e < N_EDGES) {
        atomicAdd(&g_deg_src[load_idx(src, e)], 1);
        atomicAdd(&g_deg_dst[load_idx(dst, e)], 1);
    }
}

// ---------------- single-block exclusive scan of deg_dst -> offsets, cursor ----------------
__global__ void scan_kernel() {
    const int T = 1024;
    int tid = threadIdx.x;
    int per = (N_NODES + T - 1) / T;            // 49
    int start = tid * per;
    int end = min(start + per, N_NODES);
    int sum = 0;
    for (int i = start; i < end; i++) sum += g_deg_dst[i];

    __shared__ int warp_sums[32];
    int lane = tid & 31, wid = tid >> 5;
    int v = sum;
    #pragma unroll
    for (int off = 1; off < 32; off <<= 1) {
        int t = __shfl_up_sync(0xFFFFFFFFu, v, off);
        if (lane >= off) v += t;
    }
    if (lane == 31) warp_sums[wid] = v;
    __syncthreads();
    if (wid == 0) {
        int w = warp_sums[lane];
        #pragma unroll
        for (int off = 1; off < 32; off <<= 1) {
            int t = __shfl_up_sync(0xFFFFFFFFu, w, off);
            if (lane >= off) w += t;
        }
        warp_sums[lane] = w;
    }
    __syncthreads();
    int excl = (v - sum) + (wid > 0 ? warp_sums[wid - 1] : 0);
    int run = excl;
    for (int i = start; i < end; i++) {
        g_offsets[i] = run;
        g_cursor[i]  = run;
        run += g_deg_dst[i];
    }
    if (end == N_NODES) g_offsets[N_NODES] = run;
}

// ---------------- CSR fill (+ norms, piggybacked on the wide grid) ----------------
__global__ void csr_fill_kernel(const void* src, const void* dst) {
    int e = blockIdx.x * blockDim.x + threadIdx.x;
    if (e < N_EDGES) {
        int s = load_idx(src, e);
        int d = load_idx(dst, e);
        int pos = atomicAdd(&g_cursor[d], 1);
        g_csr[pos] = s;
    }
    if (e < N_NODES) {
        g_norm_src[e] = rsqrtf(fmaxf((float)g_deg_src[e], 1.0f));
        g_norm_dst[e] = rsqrtf(fmaxf((float)g_deg_dst[e], 1.0f));
    }
}

// ---------------- GEMM1: g_h = (x @ W1) * norm_src   [50000x256]x[256x64] ----------------
#define BM 128
#define BK 16
#define BN 64
__global__ __launch_bounds__(256) void gemm1_kernel(const float* __restrict__ x,
                                                    const float* __restrict__ W1) {
    __shared__ float As[BK][BM + 4];   // As[k][m]
    __shared__ float Bs[BK][BN];       // Bs[k][n]

    int row0 = blockIdx.x * BM;
    int tid = threadIdx.x;
    int tx = tid & 15;          // col group: 4 cols each
    int ty = tid >> 4;          // row group: 8 rows each

    float acc[8][4] = {};

    for (int k0 = 0; k0 < NFEAT; k0 += BK) {
        // A tile: 128 rows x 16 k = 512 float4; 2 per thread
        #pragma unroll
        for (int i = 0; i < 2; i++) {
            int idx = tid + i * 256;
            int r  = idx >> 2;          // 0..127
            int c4 = idx & 3;           // float4 slot within k-chunk
            int grow = row0 + r;
            float4 vv = make_float4(0.f, 0.f, 0.f, 0.f);
            if (grow < N_NODES)
                vv = *(const float4*)(x + (size_t)grow * NFEAT + k0 + c4 * 4);
            As[c4 * 4 + 0][r] = vv.x;
            As[c4 * 4 + 1][r] = vv.y;
            As[c4 * 4 + 2][r] = vv.z;
            As[c4 * 4 + 3][r] = vv.w;
        }
        // B tile: 16 k x 64 cols = 256 float4; 1 per thread
        {
            int kk = tid >> 4;          // 0..15
            int c4 = tid & 15;          // 0..15
            *(float4*)&Bs[kk][c4 * 4] =
                *(const float4*)(W1 + (size_t)(k0 + kk) * NHID + c4 * 4);
        }
        __syncthreads();

        #pragma unroll
        for (int kk = 0; kk < BK; kk++) {
            float4 a0 = *(float4*)&As[kk][ty * 8];
            float4 a1 = *(float4*)&As[kk][ty * 8 + 4];
            float4 bv = *(float4*)&Bs[kk][tx * 4];
            float a[8] = {a0.x, a0.y, a0.z, a0.w, a1.x, a1.y, a1.z, a1.w};
            float b[4] = {bv.x, bv.y, bv.z, bv.w};
            #pragma unroll
            for (int i = 0; i < 8; i++)
                #pragma unroll
                for (int j = 0; j < 4; j++)
                    acc[i][j] = fmaf(a[i], b[j], acc[i][j]);
        }
        __syncthreads();
    }

    #pragma unroll
    for (int i = 0; i < 8; i++) {
        int grow = row0 + ty * 8 + i;
        if (grow < N_NODES) {
            float ns = g_norm_src[grow];
            float4 vv = make_float4(acc[i][0] * ns, acc[i][1] * ns,
                                    acc[i][2] * ns, acc[i][3] * ns);
            *(float4*)(g_h + (size_t)grow * NHID + tx * 4) = vv;
        }
    }
}

// ---------------- AGG1 + layer2 fused ----------------
// One warp per node; lane handles 2 features. After the segmented sum we apply
// bias/relu/norms, then immediately contract with W2 (warp holds the full h1
// row) and store only the 2 logits per node.
__global__ void agg1_kernel(const float* __restrict__ b1, const float* __restrict__ W2) {
    int gw = (blockIdx.x * blockDim.x + threadIdx.x) >> 5;
    int lane = threadIdx.x & 31;
    if (gw >= N_NODES) return;
    int n = gw;
    int beg = g_offsets[n], end = g_offsets[n + 1];
    float ax = 0.f, ay = 0.f;
    int i = beg;
    for (; i + 3 < end; i += 4) {
        int s0 = g_csr[i], s1 = g_csr[i + 1], s2 = g_csr[i + 2], s3 = g_csr[i + 3];
        float2 v0 = *(const float2*)(g_h + (size_t)s0 * NHID + lane * 2);
        float2 v1 = *(const float2*)(g_h + (size_t)s1 * NHID + lane * 2);
        float2 v2 = *(const float2*)(g_h + (size_t)s2 * NHID + lane * 2);
        float2 v3 = *(const float2*)(g_h + (size_t)s3 * NHID + lane * 2);
        ax += (v0.x + v1.x) + (v2.x + v3.x);
        ay += (v0.y + v1.y) + (v2.y + v3.y);
    }
    for (; i < end; i++) {
        int s0 = g_csr[i];
        float2 v0 = *(const float2*)(g_h + (size_t)s0 * NHID + lane * 2);
        ax += v0.x; ay += v0.y;
    }
    float nd = g_norm_dst[n], ns = g_norm_src[n];
    float o0 = fmaxf(fmaf(ax, nd, __ldg(&b1[lane * 2 + 0])), 0.f) * ns;
    float o1 = fmaxf(fmaf(ay, nd, __ldg(&b1[lane * 2 + 1])), 0.f) * ns;
    // layer2 contraction: logits = h1row @ W2  (W2 is [64][2])
    float w00 = __ldg(&W2[(lane * 2 + 0) * 2 + 0]);
    float w01 = __ldg(&W2[(lane * 2 + 0) * 2 + 1]);
    float w10 = __ldg(&W2[(lane * 2 + 1) * 2 + 0]);
    float w11 = __ldg(&W2[(lane * 2 + 1) * 2 + 1]);
    float c0 = fmaf(o0, w00, o1 * w10);
    float c1 = fmaf(o0, w01, o1 * w11);
    #pragma unroll
    for (int off = 16; off > 0; off >>= 1) {
        c0 += __shfl_down_sync(0xFFFFFFFFu, c0, off);
        c1 += __shfl_down_sync(0xFFFFFFFFu, c1, off);
    }
    if (lane == 0) *(float2*)(g_h2 + (size_t)n * NCLASS) = make_float2(c0, c1);
}

// ---------------- AGG2 + log_softmax ----------------
__global__ void agg2_softmax_kernel(const float* __restrict__ b2, float* __restrict__ out) {
    int n = blockIdx.x * blockDim.x + threadIdx.x;
    if (n >= N_NODES) return;
    int beg = g_offsets[n], end = g_offsets[n + 1];
    float s0 = 0.f, s1 = 0.f;
    for (int i = beg; i < end; i++) {
        int s = g_csr[i];
        float2 v = *(const float2*)(g_h2 + (size_t)s * NCLASS);
        s0 += v.x; s1 += v.y;
    }
    float nd = g_norm_dst[n];
    float l0 = fmaf(s0, nd, __ldg(&b2[0]));
    float l1 = fmaf(s1, nd, __ldg(&b2[1]));
    float m = fmaxf(l0, l1);
    float lse = m + logf(expf(l0 - m) + expf(l1 - m));
    out[n * 2 + 0] = l0 - lse;
    out[n * 2 + 1] = l1 - lse;
}

// ---------------- launch ----------------
extern "C" void kernel_launch(void* const* d_in, const int* in_sizes, int n_in,
                              void* d_out, int out_size) {
    const float* x   = (const float*)d_in[0];
    const void*  src = d_in[1];
    const void*  dst = d_in[2];
    const float* W1  = (const float*)d_in[3];
    const float* b1  = (const float*)d_in[4];
    const float* W2  = (const float*)d_in[5];
    const float* b2  = (const float*)d_in[6];
    float* out = (float*)d_out;

    init_kernel<<<(N_NODES + 255) / 256, 256>>>(src);
    count_deg_kernel<<<(N_EDGES + 255) / 256, 256>>>(src, dst);
    scan_kernel<<<1, 1024>>>();
    csr_fill_kernel<<<(N_EDGES + 255) / 256, 256>>>(src, dst);

    gemm1_kernel<<<(N_NODES + BM - 1) / BM, 256>>>(x, W1);
    agg1_kernel<<<(N_NODES * 32 + 255) / 256, 256>>>(b1, W2);
    agg2_softmax_kernel<<<(N_NODES + 255) / 256, 256>>>(b2, out);
}